// round 10
// baseline (speedup 1.0000x reference)
#include <cuda_runtime.h>
#include <cuda_bf16.h>
#include <math.h>
#include <stdint.h>

// Problem constants
#define BATCH   2
#define SEQ     2048
#define DMODEL  1024
#define NHEADS  16
#define DK      64
#define NROWS   (BATCH * SEQ)          // 4096
#define SC_LOG2 0.18033688011112042f   // (1/8) * log2(e), folded into Q

typedef unsigned short ushort_t;

// ---------------------------------------------------------------------------
// Scratch (device globals). All bf16 hi/lo.
// ---------------------------------------------------------------------------
__device__ ushort_t g_xq_hi[NROWS * DMODEL], g_xq_lo[NROWS * DMODEL];
__device__ ushort_t g_xk_hi[NROWS * DMODEL], g_xk_lo[NROWS * DMODEL];
__device__ ushort_t g_xv_hi[NROWS * DMODEL], g_xv_lo[NROWS * DMODEL];
__device__ ushort_t g_wq_hi[DMODEL * DMODEL], g_wq_lo[DMODEL * DMODEL];
__device__ ushort_t g_wk_hi[DMODEL * DMODEL], g_wk_lo[DMODEL * DMODEL];
__device__ ushort_t g_wv_hi[DMODEL * DMODEL], g_wv_lo[DMODEL * DMODEL];
__device__ ushort_t g_wo_hi[DMODEL * DMODEL], g_wo_lo[DMODEL * DMODEL];
__device__ ushort_t g_Q_hi[NROWS * DMODEL], g_Q_lo[NROWS * DMODEL];
__device__ ushort_t g_K_hi[NROWS * DMODEL], g_K_lo[NROWS * DMODEL];
__device__ ushort_t g_V_hi[NROWS * DMODEL], g_V_lo[NROWS * DMODEL];
__device__ ushort_t g_C_hi[NROWS * DMODEL], g_C_lo[NROWS * DMODEL];

// ---------------------------------------------------------------------------
// helpers
// ---------------------------------------------------------------------------
__device__ __forceinline__ uint32_t smem_u32(const void* p) {
    uint32_t a;
    asm("{ .reg .u64 t; cvta.to.shared.u64 t, %1; cvt.u32.u64 %0, t; }"
        : "=r"(a) : "l"(p));
    return a;
}

// pack two floats to bf16x2: lo half = a, hi half = b
__device__ __forceinline__ uint32_t pk2(float a, float b) {
    uint32_t r;
    asm("cvt.rn.bf16x2.f32 %0, %1, %2;" : "=r"(r) : "f"(b), "f"(a));
    return r;
}
// extract bf16x2 halves back to f32 (exact: bf16 -> f32 is a shift)
__device__ __forceinline__ float lof(uint32_t p) { return __uint_as_float(p << 16); }
__device__ __forceinline__ float hif(uint32_t p) { return __uint_as_float(p & 0xFFFF0000u); }

__device__ __forceinline__ float ex2(float x) {
    float r;
    asm("ex2.approx.f32 %0, %1;" : "=f"(r) : "f"(x));
    return r;
}

__device__ __forceinline__ void cpa16(uint32_t s, const void* g) {
    asm volatile("cp.async.cg.shared.global [%0], [%1], 16;" :: "r"(s), "l"(g));
}
#define CP_COMMIT() asm volatile("cp.async.commit_group;" ::: "memory")
#define CP_WAIT0()  asm volatile("cp.async.wait_group 0;" ::: "memory")
#define CP_WAIT1()  asm volatile("cp.async.wait_group 1;" ::: "memory")

#define LDMATRIX_X4(r0, r1, r2, r3, addr) \
    asm volatile("ldmatrix.sync.aligned.m8n8.x4.shared.b16 {%0,%1,%2,%3}, [%4];" \
        : "=r"(r0), "=r"(r1), "=r"(r2), "=r"(r3) : "r"(addr))

#define LDMATRIX_X4_T(r0, r1, r2, r3, addr) \
    asm volatile("ldmatrix.sync.aligned.m8n8.x4.trans.shared.b16 {%0,%1,%2,%3}, [%4];" \
        : "=r"(r0), "=r"(r1), "=r"(r2), "=r"(r3) : "r"(addr))

#define MMA16816(c, a, b) \
    asm volatile("mma.sync.aligned.m16n8k16.row.col.f32.bf16.bf16.f32 " \
        "{%0,%1,%2,%3}, {%4,%5,%6,%7}, {%8,%9}, {%0,%1,%2,%3};" \
        : "+f"((c)[0]), "+f"((c)[1]), "+f"((c)[2]), "+f"((c)[3]) \
        : "r"((a)[0]), "r"((a)[1]), "r"((a)[2]), "r"((a)[3]), \
          "r"((b)[0]), "r"((b)[1]))

// ---------------------------------------------------------------------------
// Batched fp32 -> (hi, lo) bf16 conversion
// ---------------------------------------------------------------------------
struct CvtBatch {
    const float* x[4];
    ushort_t* hi[4];
    ushort_t* lo[4];
};

__global__ __launch_bounds__(256) void cvt_multi_kernel(CvtBatch cb, int n4)
{
    const int j = blockIdx.y;
    int i = blockIdx.x * blockDim.x + threadIdx.x;
    if (i < n4) {
        float4 a = ((const float4*)cb.x[j])[i];
        uint32_t h0 = pk2(a.x, a.y);
        uint32_t h1 = pk2(a.z, a.w);
        ((uint2*)cb.hi[j])[i] = make_uint2(h0, h1);
        ((uint2*)cb.lo[j])[i] =
            make_uint2(pk2(a.x - lof(h0), a.y - hif(h0)),
                       pk2(a.z - lof(h1), a.w - hif(h1)));
    }
}

// ---------------------------------------------------------------------------
// Pure-bf16 split GEMM: C = oscale * (A @ B^T + bias). Batched over blockIdx.z.
// CTA tile 128x128, BK=32, cp.async 3-stage pipeline, 2 CTAs/SM.
// smem tiles are packed 64 B/row with XOR swizzle: chunk' = (c16 ^ (r>>1)) & 3
// (conflict-free ldmatrix: addresses distinct mod 128 within each 8-row phase).
// ---------------------------------------------------------------------------
struct GemmBatch {
    const ushort_t* Ahi[3];
    const ushort_t* Alo[3];
    const ushort_t* Bhi[3];
    const ushort_t* Blo[3];
    const float*    bias[3];
    ushort_t*       Chi[3];
    ushort_t*       Clo[3];
    float           oscale[3];
};

#define BSZ    (128 * 64)              // 8192 B per buffer (128 rows x 64 B)
#define GSTAGE (4 * BSZ)               // 32768 B (Ahi, Alo, Bhi, Blo)
#define GSTAGES 3
#define GSM_TOTAL (GSTAGES * GSTAGE)   // 98304 B
#define NCHUNK (DMODEL / 32)           // 32

// swizzled byte offset within one 128x64B buffer
__device__ __forceinline__ uint32_t gswz(int r, int c16) {
    return (uint32_t)(r * 64 + (((c16 ^ (r >> 1)) & 3) << 4));
}

template<int OUT_BF16>
__global__ __launch_bounds__(256, 2) void gemm_bf16_kernel(
    GemmBatch gb, float* __restrict__ Cf)
{
    extern __shared__ char sm[];
    const uint32_t smb = smem_u32(sm);

    const int z = blockIdx.z;
    const ushort_t* __restrict__ Ahi_g = gb.Ahi[z];
    const ushort_t* __restrict__ Alo_g = gb.Alo[z];
    const ushort_t* __restrict__ Bhi_g = gb.Bhi[z];
    const ushort_t* __restrict__ Blo_g = gb.Blo[z];
    const float*    __restrict__ bias  = gb.bias[z];
    const float osc = gb.oscale[z];

    const int tid = threadIdx.x;
    const int wid = tid >> 5;
    const int lane = tid & 31;
    const int wr = wid & 3;
    const int wc = wid >> 2;
    const int row0 = blockIdx.y * 128;
    const int col0 = blockIdx.x * 128;

    float acc[16][4];
#pragma unroll
    for (int t = 0; t < 16; t++)
#pragma unroll
        for (int i = 0; i < 4; i++) acc[t][i] = 0.0f;

    const int a_r = wr * 32 + (lane & 7) + ((lane >> 3) & 1) * 8;
    const int ac8 = lane >> 4;             // 16-elem-chunk select {0,1}
    const int b_r = wc * 64 + (lane >> 4) * 8 + (lane & 7);
    const int bc8 = (lane >> 3) & 1;

    // prefetch one 32-wide k-chunk into stage st (each thread: 8 x 16B)
    const int p_r  = tid >> 1;                       // 0..127
    const int p_c0 = (tid & 1) * 2;                  // c16 base {0, 2}
    auto prefetch = [&](int k0, int st) {
        uint32_t base = smb + st * GSTAGE;
#pragma unroll
        for (int cc = 0; cc < 2; cc++) {
            int c16 = p_c0 + cc;
            uint32_t so = gswz(p_r, c16);
            size_t ga = (size_t)(row0 + p_r) * DMODEL + k0 + c16 * 8;
            size_t gbo = (size_t)(col0 + p_r) * DMODEL + k0 + c16 * 8;
            cpa16(base + 0 * BSZ + so, Ahi_g + ga);
            cpa16(base + 1 * BSZ + so, Alo_g + ga);
            cpa16(base + 2 * BSZ + so, Bhi_g + gbo);
            cpa16(base + 3 * BSZ + so, Blo_g + gbo);
        }
        CP_COMMIT();
    };

    prefetch(0, 0);
    prefetch(32, 1);

    int st = 0;
    for (int kc = 0; kc < NCHUNK; kc++) {
        if (kc >= NCHUNK - 1) { CP_WAIT0(); } else { CP_WAIT1(); }
        __syncthreads();
        if (kc + 2 < NCHUNK) {
            int nst = st + 2; if (nst >= GSTAGES) nst -= GSTAGES;
            prefetch((kc + 2) * 32, nst);
        }

        const uint32_t ahi_b = smb + st * GSTAGE + 0 * BSZ;
        const uint32_t alo_b = smb + st * GSTAGE + 1 * BSZ;
        const uint32_t bhi_b = smb + st * GSTAGE + 2 * BSZ;
        const uint32_t blo_b = smb + st * GSTAGE + 3 * BSZ;

#pragma unroll
        for (int ks = 0; ks < 2; ks++) {
            uint32_t ah[2][4], al[2][4];
#pragma unroll
            for (int mt = 0; mt < 2; mt++) {
                int r = a_r + mt * 16;
                uint32_t off = gswz(r, ks * 2 + ac8);
                LDMATRIX_X4(ah[mt][0], ah[mt][1], ah[mt][2], ah[mt][3], ahi_b + off);
                LDMATRIX_X4(al[mt][0], al[mt][1], al[mt][2], al[mt][3], alo_b + off);
            }
#pragma unroll
            for (int np = 0; np < 4; np++) {
                uint32_t bh[4], bl[4];
                int r = b_r + np * 16;
                uint32_t off = gswz(r, ks * 2 + bc8);
                LDMATRIX_X4(bh[0], bh[1], bh[2], bh[3], bhi_b + off);
                LDMATRIX_X4(bl[0], bl[1], bl[2], bl[3], blo_b + off);
#pragma unroll
                for (int mt = 0; mt < 2; mt++) {
                    MMA16816(acc[mt * 8 + 2 * np], ah[mt], bh);
                    MMA16816(acc[mt * 8 + 2 * np], ah[mt], bl);
                    MMA16816(acc[mt * 8 + 2 * np], al[mt], bh);
                    MMA16816(acc[mt * 8 + 2 * np + 1], ah[mt], bh + 2);
                    MMA16816(acc[mt * 8 + 2 * np + 1], ah[mt], bl + 2);
                    MMA16816(acc[mt * 8 + 2 * np + 1], al[mt], bh + 2);
                }
            }
        }
        if (++st >= GSTAGES) st = 0;
    }

    const int er = lane >> 2;
    const int ec = (lane & 3) * 2;
#pragma unroll
    for (int mt = 0; mt < 2; mt++) {
#pragma unroll
        for (int nt = 0; nt < 8; nt++) {
            const int col = col0 + wc * 64 + nt * 8 + ec;
            const int r0 = row0 + wr * 32 + mt * 16 + er;
            float b0 = bias[col], b1 = bias[col + 1];
            float v00 = (acc[mt * 8 + nt][0] + b0) * osc;
            float v01 = (acc[mt * 8 + nt][1] + b1) * osc;
            float v10 = (acc[mt * 8 + nt][2] + b0) * osc;
            float v11 = (acc[mt * 8 + nt][3] + b1) * osc;
            if (OUT_BF16) {
                ushort_t* Chi_g = gb.Chi[z];
                ushort_t* Clo_g = gb.Clo[z];
                uint32_t h0 = pk2(v00, v01);
                uint32_t h1 = pk2(v10, v11);
                *(uint32_t*)&Chi_g[(size_t)r0 * DMODEL + col] = h0;
                *(uint32_t*)&Clo_g[(size_t)r0 * DMODEL + col] =
                    pk2(v00 - lof(h0), v01 - hif(h0));
                *(uint32_t*)&Chi_g[(size_t)(r0 + 8) * DMODEL + col] = h1;
                *(uint32_t*)&Clo_g[(size_t)(r0 + 8) * DMODEL + col] =
                    pk2(v10 - lof(h1), v11 - hif(h1));
            } else {
                *(float2*)&Cf[(size_t)r0 * DMODEL + col] = make_float2(v00, v01);
                *(float2*)&Cf[(size_t)(r0 + 8) * DMODEL + col] = make_float2(v10, v11);
            }
        }
    }
}

// ---------------------------------------------------------------------------
// Flash attention (unchanged from R9): no online max, scale folded into Q,
// Q persistent in smem, K/V double-buffered, 2 CTAs/SM.
// ---------------------------------------------------------------------------
#define LST 72
#define QSZ  (128 * LST * 2)           // 18432 B
#define ASZ  (64 * LST * 2)            // 9216 B
#define ASTAGE (4 * ASZ)               // 36864 B
#define ASM_TOTAL (2 * QSZ + 2 * ASTAGE)   // 110592 B

__global__ __launch_bounds__(256, 2) void attn_mma_kernel(
    const ushort_t* __restrict__ Qhi_g, const ushort_t* __restrict__ Qlo_g,
    const ushort_t* __restrict__ Khi_g, const ushort_t* __restrict__ Klo_g,
    const ushort_t* __restrict__ Vhi_g, const ushort_t* __restrict__ Vlo_g,
    ushort_t* __restrict__ Chi_g, ushort_t* __restrict__ Clo_g)
{
    extern __shared__ char sm[];
    const uint32_t smb = smem_u32(sm);
    const uint32_t qhi_b = smb;
    const uint32_t qlo_b = smb + QSZ;
    const uint32_t stg_b = smb + 2 * QSZ;

    const int tid = threadIdx.x;
    const int wid = tid >> 5;
    const int lane = tid & 31;
    const int b = blockIdx.z;
    const int h = blockIdx.y;
    const int q0 = blockIdx.x * 128;
    const size_t hoff = (size_t)(b * SEQ) * DMODEL + h * DK;

    const int a_r = (lane & 7) + ((lane >> 3) & 1) * 8;
    const int a_c = (lane >> 4) * 8;
    const int b_r = (lane >> 4) * 8 + (lane & 7);
    const int b_c = ((lane >> 3) & 1) * 8;
    const int v_r = ((lane >> 3) & 1) * 8 + (lane & 7);
    const int v_c = (lane >> 4) * 8;

    // ---- Stage Q (persistent) ----
    {
        const ushort_t* qh = Qhi_g + hoff + (size_t)q0 * DMODEL;
        const ushort_t* ql = Qlo_g + hoff + (size_t)q0 * DMODEL;
#pragma unroll
        for (int i = 0; i < 4; i++) {
            int idx = tid + i * 256;           // 0..1023
            int r = idx >> 3;                  // 0..127
            int ch = (idx & 7) * 8;
            uint32_t so = (uint32_t)(r * LST + ch) * 2;
            cpa16(qhi_b + so, qh + (size_t)r * DMODEL + ch);
            cpa16(qlo_b + so, ql + (size_t)r * DMODEL + ch);
        }
        CP_COMMIT();
    }

    // prefetch K/V tile
    const ushort_t* kh_g = Khi_g + hoff;
    const ushort_t* kl_g = Klo_g + hoff;
    const ushort_t* vh_g = Vhi_g + hoff;
    const ushort_t* vl_g = Vlo_g + hoff;
    auto pref_kv = [&](int kt, int st) {
        uint32_t base = stg_b + st * ASTAGE;
#pragma unroll
        for (int i = 0; i < 2; i++) {
            int idx = tid + i * 256;           // 0..511
            int r = idx >> 3;                  // 0..63
            int ch = (idx & 7) * 8;
            uint32_t so = (uint32_t)(r * LST + ch) * 2;
            size_t g = (size_t)(kt + r) * DMODEL + ch;
            cpa16(base + 0 * ASZ + so, kh_g + g);
            cpa16(base + 1 * ASZ + so, kl_g + g);
            cpa16(base + 2 * ASZ + so, vh_g + g);
            cpa16(base + 3 * ASZ + so, vl_g + g);
        }
        CP_COMMIT();
    };

    pref_kv(0, 0);

    float o[8][4];
#pragma unroll
    for (int j = 0; j < 8; j++)
#pragma unroll
        for (int i = 0; i < 4; i++) o[j][i] = 0.0f;
    float l0 = 0.0f, l1 = 0.0f;

    for (int t = 0; t < SEQ / 64; t++) {
        const int st = t & 1;
        CP_WAIT0();
        __syncthreads();
        if (t + 1 < SEQ / 64) pref_kv((t + 1) * 64, st ^ 1);

        const uint32_t skh = stg_b + st * ASTAGE + 0 * ASZ;
        const uint32_t skl = stg_b + st * ASTAGE + 1 * ASZ;
        const uint32_t svh = stg_b + st * ASTAGE + 2 * ASZ;
        const uint32_t svl = stg_b + st * ASTAGE + 3 * ASZ;

        // ---- S = Q K^T ----
        float s[8][4];
#pragma unroll
        for (int j = 0; j < 8; j++)
#pragma unroll
            for (int i = 0; i < 4; i++) s[j][i] = 0.0f;

#pragma unroll
        for (int ks = 0; ks < 4; ks++) {
            uint32_t qh[4], ql[4];
            uint32_t qoff = (uint32_t)((wid * 16 + a_r) * LST + ks * 16 + a_c) * 2;
            LDMATRIX_X4(qh[0], qh[1], qh[2], qh[3], qhi_b + qoff);
            LDMATRIX_X4(ql[0], ql[1], ql[2], ql[3], qlo_b + qoff);
#pragma unroll
            for (int np = 0; np < 4; np++) {
                uint32_t kh[4], kl[4];
                uint32_t off = (uint32_t)((np * 16 + b_r) * LST + ks * 16 + b_c) * 2;
                LDMATRIX_X4(kh[0], kh[1], kh[2], kh[3], skh + off);
                LDMATRIX_X4(kl[0], kl[1], kl[2], kl[3], skl + off);
                MMA16816(s[2 * np], qh, kh);
                MMA16816(s[2 * np], qh, kl);
                MMA16816(s[2 * np], ql, kh);
                MMA16816(s[2 * np + 1], qh, kh + 2);
                MMA16816(s[2 * np + 1], qh, kl + 2);
                MMA16816(s[2 * np + 1], ql, kh + 2);
            }
        }

        // ---- p = exp2(S); accumulate l ----
#pragma unroll
        for (int j = 0; j < 8; j++) {
            s[j][0] = ex2(s[j][0]);
            s[j][1] = ex2(s[j][1]);
            s[j][2] = ex2(s[j][2]);
            s[j][3] = ex2(s[j][3]);
            l0 += s[j][0] + s[j][1];
            l1 += s[j][2] + s[j][3];
        }

        // ---- O += P V ----
#pragma unroll
        for (int ks = 0; ks < 4; ks++) {
            const float* pe = s[2 * ks];
            const float* po = s[2 * ks + 1];
            uint32_t ph[4], pl[4];
            ph[0] = pk2(pe[0], pe[1]);
            ph[1] = pk2(pe[2], pe[3]);
            ph[2] = pk2(po[0], po[1]);
            ph[3] = pk2(po[2], po[3]);
            pl[0] = pk2(pe[0] - lof(ph[0]), pe[1] - hif(ph[0]));
            pl[1] = pk2(pe[2] - lof(ph[1]), pe[3] - hif(ph[1]));
            pl[2] = pk2(po[0] - lof(ph[2]), po[1] - hif(ph[2]));
            pl[3] = pk2(po[2] - lof(ph[3]), po[3] - hif(ph[3]));
#pragma unroll
            for (int np = 0; np < 4; np++) {
                uint32_t vh[4], vl[4];
                uint32_t off = (uint32_t)((ks * 16 + v_r) * LST + np * 16 + v_c) * 2;
                LDMATRIX_X4_T(vh[0], vh[1], vh[2], vh[3], svh + off);
                LDMATRIX_X4_T(vl[0], vl[1], vl[2], vl[3], svl + off);
                MMA16816(o[2 * np], ph, vh);
                MMA16816(o[2 * np], pl, vh);
                MMA16816(o[2 * np], ph, vl);
                MMA16816(o[2 * np + 1], ph, vh + 2);
                MMA16816(o[2 * np + 1], pl, vh + 2);
                MMA16816(o[2 * np + 1], ph, vl + 2);
            }
        }
    }

    // ---- final l reduction ----
    l0 += __shfl_xor_sync(0xFFFFFFFFu, l0, 1);
    l0 += __shfl_xor_sync(0xFFFFFFFFu, l0, 2);
    l1 += __shfl_xor_sync(0xFFFFFFFFu, l1, 1);
    l1 += __shfl_xor_sync(0xFFFFFFFFu, l1, 2);

    // ---- epilogue ----
    const float inv0 = 1.0f / l0;
    const float inv1 = 1.0f / l1;
    const int r0 = q0 + wid * 16 + (lane >> 2);
    const int ec = (lane & 3) * 2;
    ushort_t* chb = Chi_g + hoff;
    ushort_t* clb = Clo_g + hoff;
#pragma unroll
    for (int j = 0; j < 8; j++) {
        int col = j * 8 + ec;
        float v0 = o[j][0] * inv0, v1 = o[j][1] * inv0;
        float v2 = o[j][2] * inv1, v3 = o[j][3] * inv1;
        uint32_t h0 = pk2(v0, v1);
        uint32_t h1 = pk2(v2, v3);
        *(uint32_t*)&chb[(size_t)r0 * DMODEL + col] = h0;
        *(uint32_t*)&clb[(size_t)r0 * DMODEL + col] = pk2(v0 - lof(h0), v1 - hif(h0));
        *(uint32_t*)&chb[(size_t)(r0 + 8) * DMODEL + col] = h1;
        *(uint32_t*)&clb[(size_t)(r0 + 8) * DMODEL + col] = pk2(v2 - lof(h1), v3 - hif(h1));
    }
}

// ---------------------------------------------------------------------------
// Launch
// ---------------------------------------------------------------------------
extern "C" void kernel_launch(void* const* d_in, const int* in_sizes, int n_in,
                              void* d_out, int out_size)
{
    const float* query = (const float*)d_in[0];
    const float* key_  = (const float*)d_in[1];
    const float* value = (const float*)d_in[2];
    const float* wq = (const float*)d_in[3];
    const float* bq = (const float*)d_in[4];
    const float* wk = (const float*)d_in[5];
    const float* bk = (const float*)d_in[6];
    const float* wv = (const float*)d_in[7];
    const float* bv = (const float*)d_in[8];
    const float* wo = (const float*)d_in[9];
    const float* bo = (const float*)d_in[10];
    float* out = (float*)d_out;

    ushort_t *xqh, *xql, *xkh, *xkl, *xvh, *xvl;
    ushort_t *wqh, *wql, *wkh, *wkl, *wvh, *wvl, *woh, *wol;
    ushort_t *Qh, *Ql, *Kh, *Kl, *Vh, *Vl, *Ch, *Cl;
    cudaGetSymbolAddress((void**)&xqh, g_xq_hi); cudaGetSymbolAddress((void**)&xql, g_xq_lo);
    cudaGetSymbolAddress((void**)&xkh, g_xk_hi); cudaGetSymbolAddress((void**)&xkl, g_xk_lo);
    cudaGetSymbolAddress((void**)&xvh, g_xv_hi); cudaGetSymbolAddress((void**)&xvl, g_xv_lo);
    cudaGetSymbolAddress((void**)&wqh, g_wq_hi); cudaGetSymbolAddress((void**)&wql, g_wq_lo);
    cudaGetSymbolAddress((void**)&wkh, g_wk_hi); cudaGetSymbolAddress((void**)&wkl, g_wk_lo);
    cudaGetSymbolAddress((void**)&wvh, g_wv_hi); cudaGetSymbolAddress((void**)&wvl, g_wv_lo);
    cudaGetSymbolAddress((void**)&woh, g_wo_hi); cudaGetSymbolAddress((void**)&wol, g_wo_lo);
    cudaGetSymbolAddress((void**)&Qh, g_Q_hi);   cudaGetSymbolAddress((void**)&Ql, g_Q_lo);
    cudaGetSymbolAddress((void**)&Kh, g_K_hi);   cudaGetSymbolAddress((void**)&Kl, g_K_lo);
    cudaGetSymbolAddress((void**)&Vh, g_V_hi);   cudaGetSymbolAddress((void**)&Vl, g_V_lo);
    cudaGetSymbolAddress((void**)&Ch, g_C_hi);   cudaGetSymbolAddress((void**)&Cl, g_C_lo);

    cudaFuncSetAttribute(gemm_bf16_kernel<0>,
                         cudaFuncAttributeMaxDynamicSharedMemorySize, GSM_TOTAL);
    cudaFuncSetAttribute(gemm_bf16_kernel<1>,
                         cudaFuncAttributeMaxDynamicSharedMemorySize, GSM_TOTAL);
    cudaFuncSetAttribute(attn_mma_kernel,
                         cudaFuncAttributeMaxDynamicSharedMemorySize, ASM_TOTAL);

    // 1. Convert inputs + weights to hi/lo bf16 (2 batched launches)
    const int n4_in = NROWS * DMODEL / 4;
    const int n4_w  = DMODEL * DMODEL / 4;
    {
        CvtBatch ci = {};
        ci.x[0] = query; ci.hi[0] = xqh; ci.lo[0] = xql;
        ci.x[1] = key_;  ci.hi[1] = xkh; ci.lo[1] = xkl;
        ci.x[2] = value; ci.hi[2] = xvh; ci.lo[2] = xvl;
        dim3 g(n4_in / 256, 3);
        cvt_multi_kernel<<<g, 256>>>(ci, n4_in);

        CvtBatch cw = {};
        cw.x[0] = wq; cw.hi[0] = wqh; cw.lo[0] = wql;
        cw.x[1] = wk; cw.hi[1] = wkh; cw.lo[1] = wkl;
        cw.x[2] = wv; cw.hi[2] = wvh; cw.lo[2] = wvl;
        cw.x[3] = wo; cw.hi[3] = woh; cw.lo[3] = wol;
        dim3 g2(n4_w / 256, 4);
        cvt_multi_kernel<<<g2, 256>>>(cw, n4_w);
    }

    // 2. Fused QKV projections (one launch, grid.z = 3).
    //    Q output pre-scaled by (1/8)*log2(e) so attention exp2's raw S.
    {
        GemmBatch gb = {};
        gb.Ahi[0] = xqh; gb.Alo[0] = xql; gb.Bhi[0] = wqh; gb.Blo[0] = wql;
        gb.bias[0] = bq; gb.Chi[0] = Qh;  gb.Clo[0] = Ql;  gb.oscale[0] = SC_LOG2;
        gb.Ahi[1] = xkh; gb.Alo[1] = xkl; gb.Bhi[1] = wkh; gb.Blo[1] = wkl;
        gb.bias[1] = bk; gb.Chi[1] = Kh;  gb.Clo[1] = Kl;  gb.oscale[1] = 1.0f;
        gb.Ahi[2] = xvh; gb.Alo[2] = xvl; gb.Bhi[2] = wvh; gb.Blo[2] = wvl;
        gb.bias[2] = bv; gb.Chi[2] = Vh;  gb.Clo[2] = Vl;  gb.oscale[2] = 1.0f;
        dim3 ggrid(DMODEL / 128, NROWS / 128, 3);
        gemm_bf16_kernel<1><<<ggrid, 256, GSM_TOTAL>>>(gb, nullptr);
    }

    // 3. Attention
    dim3 agrid(SEQ / 128, NHEADS, BATCH);
    attn_mma_kernel<<<agrid, 256, ASM_TOTAL>>>(Qh, Ql, Kh, Kl, Vh, Vl, Ch, Cl);

    // 4. Output projection (fp32 out)
    {
        GemmBatch gb = {};
        gb.Ahi[0] = Ch; gb.Alo[0] = Cl; gb.Bhi[0] = woh; gb.Blo[0] = wol;
        gb.bias[0] = bo; gb.oscale[0] = 1.0f;
        dim3 ggrid(DMODEL / 128, NROWS / 128, 1);
        gemm_bf16_kernel<0><<<ggrid, 256, GSM_TOTAL>>>(gb, out);
    }
}

// round 12
// speedup vs baseline: 1.0560x; 1.0560x over previous
#include <cuda_runtime.h>
#include <cuda_bf16.h>
#include <math.h>
#include <stdint.h>

// Problem constants
#define BATCH   2
#define SEQ     2048
#define DMODEL  1024
#define NHEADS  16
#define DK      64
#define NROWS   (BATCH * SEQ)          // 4096
#define SC_LOG2 0.18033688011112042f   // (1/8) * log2(e), folded into Q

typedef unsigned short ushort_t;

// ---------------------------------------------------------------------------
// Scratch (device globals). All bf16 hi/lo.
// ---------------------------------------------------------------------------
__device__ ushort_t g_xq_hi[NROWS * DMODEL], g_xq_lo[NROWS * DMODEL];
__device__ ushort_t g_xk_hi[NROWS * DMODEL], g_xk_lo[NROWS * DMODEL];
__device__ ushort_t g_xv_hi[NROWS * DMODEL], g_xv_lo[NROWS * DMODEL];
__device__ ushort_t g_wq_hi[DMODEL * DMODEL], g_wq_lo[DMODEL * DMODEL];
__device__ ushort_t g_wk_hi[DMODEL * DMODEL], g_wk_lo[DMODEL * DMODEL];
__device__ ushort_t g_wv_hi[DMODEL * DMODEL], g_wv_lo[DMODEL * DMODEL];
__device__ ushort_t g_wo_hi[DMODEL * DMODEL], g_wo_lo[DMODEL * DMODEL];
__device__ ushort_t g_Q_hi[NROWS * DMODEL], g_Q_lo[NROWS * DMODEL];
__device__ ushort_t g_K_hi[NROWS * DMODEL], g_K_lo[NROWS * DMODEL];
__device__ ushort_t g_V_hi[NROWS * DMODEL], g_V_lo[NROWS * DMODEL];
__device__ ushort_t g_C_hi[NROWS * DMODEL], g_C_lo[NROWS * DMODEL];

// Persistent-kernel work tickets: [0]=QKV gemm, [1]=attention, [2]=wo gemm.
// Reset by cvt_multi_kernel (which runs first every replay).
__device__ unsigned int g_tickets[4];

// ---------------------------------------------------------------------------
// helpers
// ---------------------------------------------------------------------------
__device__ __forceinline__ uint32_t smem_u32(const void* p) {
    uint32_t a;
    asm("{ .reg .u64 t; cvta.to.shared.u64 t, %1; cvt.u32.u64 %0, t; }"
        : "=r"(a) : "l"(p));
    return a;
}

// pack two floats to bf16x2: lo half = a, hi half = b
__device__ __forceinline__ uint32_t pk2(float a, float b) {
    uint32_t r;
    asm("cvt.rn.bf16x2.f32 %0, %1, %2;" : "=r"(r) : "f"(b), "f"(a));
    return r;
}
// extract bf16x2 halves back to f32 (exact)
__device__ __forceinline__ float lof(uint32_t p) { return __uint_as_float(p << 16); }
__device__ __forceinline__ float hif(uint32_t p) { return __uint_as_float(p & 0xFFFF0000u); }

__device__ __forceinline__ float ex2(float x) {
    float r;
    asm("ex2.approx.f32 %0, %1;" : "=f"(r) : "f"(x));
    return r;
}

__device__ __forceinline__ void cpa16(uint32_t s, const void* g) {
    asm volatile("cp.async.cg.shared.global [%0], [%1], 16;" :: "r"(s), "l"(g));
}
#define CP_COMMIT() asm volatile("cp.async.commit_group;" ::: "memory")
#define CP_WAIT0()  asm volatile("cp.async.wait_group 0;" ::: "memory")

#define LDMATRIX_X4(r0, r1, r2, r3, addr) \
    asm volatile("ldmatrix.sync.aligned.m8n8.x4.shared.b16 {%0,%1,%2,%3}, [%4];" \
        : "=r"(r0), "=r"(r1), "=r"(r2), "=r"(r3) : "r"(addr))

#define LDMATRIX_X4_T(r0, r1, r2, r3, addr) \
    asm volatile("ldmatrix.sync.aligned.m8n8.x4.trans.shared.b16 {%0,%1,%2,%3}, [%4];" \
        : "=r"(r0), "=r"(r1), "=r"(r2), "=r"(r3) : "r"(addr))

#define MMA16816(c, a, b) \
    asm volatile("mma.sync.aligned.m16n8k16.row.col.f32.bf16.bf16.f32 " \
        "{%0,%1,%2,%3}, {%4,%5,%6,%7}, {%8,%9}, {%0,%1,%2,%3};" \
        : "+f"((c)[0]), "+f"((c)[1]), "+f"((c)[2]), "+f"((c)[3]) \
        : "r"((a)[0]), "r"((a)[1]), "r"((a)[2]), "r"((a)[3]), \
          "r"((b)[0]), "r"((b)[1]))

// ---------------------------------------------------------------------------
// Batched fp32 -> (hi, lo) bf16 conversion (7 arrays in one launch).
// Also resets the persistent-kernel ticket counters.
// ---------------------------------------------------------------------------
struct CvtBatch {
    const float* x[7];
    ushort_t* hi[7];
    ushort_t* lo[7];
    int n4[7];
};

__global__ __launch_bounds__(256) void cvt_multi_kernel(CvtBatch cb)
{
    if (blockIdx.x == 0 && blockIdx.y == 0 && threadIdx.x < 4)
        g_tickets[threadIdx.x] = 0u;

    const int j = blockIdx.y;
    int i = blockIdx.x * blockDim.x + threadIdx.x;
    if (i < cb.n4[j]) {
        float4 a = ((const float4*)cb.x[j])[i];
        uint32_t h0 = pk2(a.x, a.y);
        uint32_t h1 = pk2(a.z, a.w);
        ((uint2*)cb.hi[j])[i] = make_uint2(h0, h1);
        ((uint2*)cb.lo[j])[i] =
            make_uint2(pk2(a.x - lof(h0), a.y - hif(h0)),
                       pk2(a.z - lof(h1), a.w - hif(h1)));
    }
}

// ---------------------------------------------------------------------------
// Pure-bf16 split GEMM (persistent): C = oscale * (A @ B^T + bias).
// Tiles: 128x128, item = z*256 + by*8 + bx. BK=32, cp.async double-buffered,
// padded smem (LSTR=40), 2 CTAs/SM.
// ---------------------------------------------------------------------------
struct GemmBatch {
    const ushort_t* Ahi[3];
    const ushort_t* Alo[3];
    const ushort_t* Bhi[3];
    const ushort_t* Blo[3];
    const float*    bias[3];
    ushort_t*       Chi[3];
    ushort_t*       Clo[3];
    float           oscale[3];
};

#define LSTR 40
#define GSZ    (128 * LSTR * 2)        // 10240 B
#define GSTAGE (4 * GSZ)               // 40960 B
#define GSM_TOTAL (2 * GSTAGE)         // 81920 B

template<int OUT_BF16>
__global__ __launch_bounds__(256, 2) void gemm_bf16_kernel(
    GemmBatch gb, float* __restrict__ Cf, int ntiles, int ticket_idx)
{
    extern __shared__ char sm[];
    __shared__ int s_item;
    const uint32_t smb = smem_u32(sm);

    const int tid = threadIdx.x;
    const int wid = tid >> 5;
    const int lane = tid & 31;
    const int wr = wid & 3;
    const int wc = wid >> 2;

    const int a_rb = wr * 32 + (lane & 7) + ((lane >> 3) & 1) * 8;
    const int a_c = (lane >> 4) * 8;
    const int b_rb = wc * 64 + (lane >> 4) * 8 + (lane & 7);
    const int b_c = ((lane >> 3) & 1) * 8;

    for (;;) {
        if (tid == 0) s_item = (int)atomicAdd(&g_tickets[ticket_idx], 1u);
        __syncthreads();
        const int item = s_item;
        if (item >= ntiles) return;

        const int z = item >> 8;            // 256 tiles per matrix
        const int rem = item & 255;
        const int col0 = (rem & 7) * 128;
        const int row0 = (rem >> 3) * 128;

        const ushort_t* __restrict__ Ahi_g = gb.Ahi[z];
        const ushort_t* __restrict__ Alo_g = gb.Alo[z];
        const ushort_t* __restrict__ Bhi_g = gb.Bhi[z];
        const ushort_t* __restrict__ Blo_g = gb.Blo[z];
        const float*    __restrict__ bias  = gb.bias[z];
        const float osc = gb.oscale[z];

        float acc[16][4];
#pragma unroll
        for (int t = 0; t < 16; t++)
#pragma unroll
            for (int i = 0; i < 4; i++) acc[t][i] = 0.0f;

        auto prefetch = [&](int k0, int st) {
            uint32_t base = smb + st * GSTAGE;
#pragma unroll
            for (int i = 0; i < 2; i++) {
                int idx = tid + i * 256;
                int row = idx >> 2;
                int ch = (idx & 3) * 8;
                uint32_t so = (uint32_t)(row * LSTR + ch) * 2;
                size_t ga = (size_t)(row0 + row) * DMODEL + k0 + ch;
                size_t gbo = (size_t)(col0 + row) * DMODEL + k0 + ch;
                cpa16(base + 0 * GSZ + so, Ahi_g + ga);
                cpa16(base + 1 * GSZ + so, Alo_g + ga);
                cpa16(base + 2 * GSZ + so, Bhi_g + gbo);
                cpa16(base + 3 * GSZ + so, Blo_g + gbo);
            }
            CP_COMMIT();
        };

        prefetch(0, 0);

        for (int kc = 0; kc < DMODEL / 32; kc++) {
            const int st = kc & 1;
            CP_WAIT0();
            __syncthreads();
            if (kc + 1 < DMODEL / 32) prefetch((kc + 1) * 32, st ^ 1);

            const uint32_t ahi_b = smb + st * GSTAGE + 0 * GSZ;
            const uint32_t alo_b = smb + st * GSTAGE + 1 * GSZ;
            const uint32_t bhi_b = smb + st * GSTAGE + 2 * GSZ;
            const uint32_t blo_b = smb + st * GSTAGE + 3 * GSZ;

#pragma unroll
            for (int ks = 0; ks < 2; ks++) {
                const int kk = ks * 16;
                uint32_t ah[2][4], al[2][4];
#pragma unroll
                for (int mt = 0; mt < 2; mt++) {
                    uint32_t off = (uint32_t)((a_rb + mt * 16) * LSTR + kk + a_c) * 2;
                    LDMATRIX_X4(ah[mt][0], ah[mt][1], ah[mt][2], ah[mt][3], ahi_b + off);
                    LDMATRIX_X4(al[mt][0], al[mt][1], al[mt][2], al[mt][3], alo_b + off);
                }
#pragma unroll
                for (int np = 0; np < 4; np++) {
                    uint32_t bh[4], bl[4];
                    uint32_t off = (uint32_t)((b_rb + np * 16) * LSTR + kk + b_c) * 2;
                    LDMATRIX_X4(bh[0], bh[1], bh[2], bh[3], bhi_b + off);
                    LDMATRIX_X4(bl[0], bl[1], bl[2], bl[3], blo_b + off);
#pragma unroll
                    for (int mt = 0; mt < 2; mt++) {
                        MMA16816(acc[mt * 8 + 2 * np], ah[mt], bh);
                        MMA16816(acc[mt * 8 + 2 * np], ah[mt], bl);
                        MMA16816(acc[mt * 8 + 2 * np], al[mt], bh);
                        MMA16816(acc[mt * 8 + 2 * np + 1], ah[mt], bh + 2);
                        MMA16816(acc[mt * 8 + 2 * np + 1], ah[mt], bl + 2);
                        MMA16816(acc[mt * 8 + 2 * np + 1], al[mt], bh + 2);
                    }
                }
            }
        }

        const int er = lane >> 2;
        const int ec = (lane & 3) * 2;
#pragma unroll
        for (int mt = 0; mt < 2; mt++) {
#pragma unroll
            for (int nt = 0; nt < 8; nt++) {
                const int col = col0 + wc * 64 + nt * 8 + ec;
                const int r0 = row0 + wr * 32 + mt * 16 + er;
                float b0 = bias[col], b1 = bias[col + 1];
                float v00 = (acc[mt * 8 + nt][0] + b0) * osc;
                float v01 = (acc[mt * 8 + nt][1] + b1) * osc;
                float v10 = (acc[mt * 8 + nt][2] + b0) * osc;
                float v11 = (acc[mt * 8 + nt][3] + b1) * osc;
                if (OUT_BF16) {
                    ushort_t* Chi_g = gb.Chi[z];
                    ushort_t* Clo_g = gb.Clo[z];
                    uint32_t h0 = pk2(v00, v01);
                    uint32_t h1 = pk2(v10, v11);
                    *(uint32_t*)&Chi_g[(size_t)r0 * DMODEL + col] = h0;
                    *(uint32_t*)&Clo_g[(size_t)r0 * DMODEL + col] =
                        pk2(v00 - lof(h0), v01 - hif(h0));
                    *(uint32_t*)&Chi_g[(size_t)(r0 + 8) * DMODEL + col] = h1;
                    *(uint32_t*)&Clo_g[(size_t)(r0 + 8) * DMODEL + col] =
                        pk2(v10 - lof(h1), v11 - hif(h1));
                } else {
                    *(float2*)&Cf[(size_t)r0 * DMODEL + col] = make_float2(v00, v01);
                    *(float2*)&Cf[(size_t)(r0 + 8) * DMODEL + col] = make_float2(v10, v11);
                }
            }
        }
    }
}

// ---------------------------------------------------------------------------
// Flash attention (persistent): no online max, scale folded into Q,
// Q persistent in smem, K/V double-buffered, 2 CTAs/SM.
// Work item = b*256 + h*16 + qtile.
// ---------------------------------------------------------------------------
#define LST 72
#define QSZ  (128 * LST * 2)           // 18432 B
#define ASZ  (64 * LST * 2)            // 9216 B
#define ASTAGE (4 * ASZ)               // 36864 B
#define ASM_TOTAL (2 * QSZ + 2 * ASTAGE)   // 110592 B
#define ATTN_ITEMS 512

__global__ __launch_bounds__(256, 2) void attn_mma_kernel(
    const ushort_t* __restrict__ Qhi_g, const ushort_t* __restrict__ Qlo_g,
    const ushort_t* __restrict__ Khi_g, const ushort_t* __restrict__ Klo_g,
    const ushort_t* __restrict__ Vhi_g, const ushort_t* __restrict__ Vlo_g,
    ushort_t* __restrict__ Chi_g, ushort_t* __restrict__ Clo_g)
{
    extern __shared__ char sm[];
    __shared__ int s_item;
    const uint32_t smb = smem_u32(sm);
    const uint32_t qhi_b = smb;
    const uint32_t qlo_b = smb + QSZ;
    const uint32_t stg_b = smb + 2 * QSZ;

    const int tid = threadIdx.x;
    const int wid = tid >> 5;
    const int lane = tid & 31;

    const int a_r = (lane & 7) + ((lane >> 3) & 1) * 8;
    const int a_c = (lane >> 4) * 8;
    const int b_r = (lane >> 4) * 8 + (lane & 7);
    const int b_c = ((lane >> 3) & 1) * 8;
    const int v_r = ((lane >> 3) & 1) * 8 + (lane & 7);
    const int v_c = (lane >> 4) * 8;

    for (;;) {
        if (tid == 0) s_item = (int)atomicAdd(&g_tickets[1], 1u);
        __syncthreads();
        const int item = s_item;
        if (item >= ATTN_ITEMS) return;

        const int q0 = (item & 15) * 128;
        const int h = (item >> 4) & 15;
        const int b = item >> 8;
        const size_t hoff = (size_t)(b * SEQ) * DMODEL + h * DK;

        // ---- Stage Q (persistent region) ----
        {
            const ushort_t* qh = Qhi_g + hoff + (size_t)q0 * DMODEL;
            const ushort_t* ql = Qlo_g + hoff + (size_t)q0 * DMODEL;
#pragma unroll
            for (int i = 0; i < 4; i++) {
                int idx = tid + i * 256;
                int r = idx >> 3;
                int ch = (idx & 7) * 8;
                uint32_t so = (uint32_t)(r * LST + ch) * 2;
                cpa16(qhi_b + so, qh + (size_t)r * DMODEL + ch);
                cpa16(qlo_b + so, ql + (size_t)r * DMODEL + ch);
            }
            CP_COMMIT();
        }

        const ushort_t* kh_g = Khi_g + hoff;
        const ushort_t* kl_g = Klo_g + hoff;
        const ushort_t* vh_g = Vhi_g + hoff;
        const ushort_t* vl_g = Vlo_g + hoff;
        auto pref_kv = [&](int kt, int st) {
            uint32_t base = stg_b + st * ASTAGE;
#pragma unroll
            for (int i = 0; i < 2; i++) {
                int idx = tid + i * 256;
                int r = idx >> 3;
                int ch = (idx & 7) * 8;
                uint32_t so = (uint32_t)(r * LST + ch) * 2;
                size_t g = (size_t)(kt + r) * DMODEL + ch;
                cpa16(base + 0 * ASZ + so, kh_g + g);
                cpa16(base + 1 * ASZ + so, kl_g + g);
                cpa16(base + 2 * ASZ + so, vh_g + g);
                cpa16(base + 3 * ASZ + so, vl_g + g);
            }
            CP_COMMIT();
        };

        pref_kv(0, 0);

        float o[8][4];
#pragma unroll
        for (int j = 0; j < 8; j++)
#pragma unroll
            for (int i = 0; i < 4; i++) o[j][i] = 0.0f;
        float l0 = 0.0f, l1 = 0.0f;

        for (int t = 0; t < SEQ / 64; t++) {
            const int st = t & 1;
            CP_WAIT0();
            __syncthreads();
            if (t + 1 < SEQ / 64) pref_kv((t + 1) * 64, st ^ 1);

            const uint32_t skh = stg_b + st * ASTAGE + 0 * ASZ;
            const uint32_t skl = stg_b + st * ASTAGE + 1 * ASZ;
            const uint32_t svh = stg_b + st * ASTAGE + 2 * ASZ;
            const uint32_t svl = stg_b + st * ASTAGE + 3 * ASZ;

            // ---- S = Q K^T ----
            float s[8][4];
#pragma unroll
            for (int j = 0; j < 8; j++)
#pragma unroll
                for (int i = 0; i < 4; i++) s[j][i] = 0.0f;

#pragma unroll
            for (int ks = 0; ks < 4; ks++) {
                uint32_t qh[4], ql[4];
                uint32_t qoff = (uint32_t)((wid * 16 + a_r) * LST + ks * 16 + a_c) * 2;
                LDMATRIX_X4(qh[0], qh[1], qh[2], qh[3], qhi_b + qoff);
                LDMATRIX_X4(ql[0], ql[1], ql[2], ql[3], qlo_b + qoff);
#pragma unroll
                for (int np = 0; np < 4; np++) {
                    uint32_t kh[4], kl[4];
                    uint32_t off = (uint32_t)((np * 16 + b_r) * LST + ks * 16 + b_c) * 2;
                    LDMATRIX_X4(kh[0], kh[1], kh[2], kh[3], skh + off);
                    LDMATRIX_X4(kl[0], kl[1], kl[2], kl[3], skl + off);
                    MMA16816(s[2 * np], qh, kh);
                    MMA16816(s[2 * np], qh, kl);
                    MMA16816(s[2 * np], ql, kh);
                    MMA16816(s[2 * np + 1], qh, kh + 2);
                    MMA16816(s[2 * np + 1], qh, kl + 2);
                    MMA16816(s[2 * np + 1], ql, kh + 2);
                }
            }

            // ---- p = exp2(S); accumulate l ----
#pragma unroll
            for (int j = 0; j < 8; j++) {
                s[j][0] = ex2(s[j][0]);
                s[j][1] = ex2(s[j][1]);
                s[j][2] = ex2(s[j][2]);
                s[j][3] = ex2(s[j][3]);
                l0 += s[j][0] + s[j][1];
                l1 += s[j][2] + s[j][3];
            }

            // ---- O += P V ----
#pragma unroll
            for (int ks = 0; ks < 4; ks++) {
                const float* pe = s[2 * ks];
                const float* po = s[2 * ks + 1];
                uint32_t ph[4], pl[4];
                ph[0] = pk2(pe[0], pe[1]);
                ph[1] = pk2(pe[2], pe[3]);
                ph[2] = pk2(po[0], po[1]);
                ph[3] = pk2(po[2], po[3]);
                pl[0] = pk2(pe[0] - lof(ph[0]), pe[1] - hif(ph[0]));
                pl[1] = pk2(pe[2] - lof(ph[1]), pe[3] - hif(ph[1]));
                pl[2] = pk2(po[0] - lof(ph[2]), po[1] - hif(ph[2]));
                pl[3] = pk2(po[2] - lof(ph[3]), po[3] - hif(ph[3]));
#pragma unroll
                for (int np = 0; np < 4; np++) {
                    uint32_t vh[4], vl[4];
                    uint32_t off = (uint32_t)((ks * 16 + v_r) * LST + np * 16 + v_c) * 2;
                    LDMATRIX_X4_T(vh[0], vh[1], vh[2], vh[3], svh + off);
                    LDMATRIX_X4_T(vl[0], vl[1], vl[2], vl[3], svl + off);
                    MMA16816(o[2 * np], ph, vh);
                    MMA16816(o[2 * np], pl, vh);
                    MMA16816(o[2 * np], ph, vl);
                    MMA16816(o[2 * np + 1], ph, vh + 2);
                    MMA16816(o[2 * np + 1], pl, vh + 2);
                    MMA16816(o[2 * np + 1], ph, vl + 2);
                }
            }
        }

        // ---- final l reduction ----
        l0 += __shfl_xor_sync(0xFFFFFFFFu, l0, 1);
        l0 += __shfl_xor_sync(0xFFFFFFFFu, l0, 2);
        l1 += __shfl_xor_sync(0xFFFFFFFFu, l1, 1);
        l1 += __shfl_xor_sync(0xFFFFFFFFu, l1, 2);

        // ---- epilogue ----
        const float inv0 = 1.0f / l0;
        const float inv1 = 1.0f / l1;
        const int r0 = q0 + wid * 16 + (lane >> 2);
        const int ec = (lane & 3) * 2;
        ushort_t* chb = Chi_g + hoff;
        ushort_t* clb = Clo_g + hoff;
#pragma unroll
        for (int j = 0; j < 8; j++) {
            int col = j * 8 + ec;
            float v0 = o[j][0] * inv0, v1 = o[j][1] * inv0;
            float v2 = o[j][2] * inv1, v3 = o[j][3] * inv1;
            uint32_t h0 = pk2(v0, v1);
            uint32_t h1 = pk2(v2, v3);
            *(uint32_t*)&chb[(size_t)r0 * DMODEL + col] = h0;
            *(uint32_t*)&clb[(size_t)r0 * DMODEL + col] = pk2(v0 - lof(h0), v1 - hif(h0));
            *(uint32_t*)&chb[(size_t)(r0 + 8) * DMODEL + col] = h1;
            *(uint32_t*)&clb[(size_t)(r0 + 8) * DMODEL + col] = pk2(v2 - lof(h1), v3 - hif(h1));
        }
    }
}

// ---------------------------------------------------------------------------
// Launch
// ---------------------------------------------------------------------------
extern "C" void kernel_launch(void* const* d_in, const int* in_sizes, int n_in,
                              void* d_out, int out_size)
{
    const float* query = (const float*)d_in[0];
    const float* key_  = (const float*)d_in[1];
    const float* value = (const float*)d_in[2];
    const float* wq = (const float*)d_in[3];
    const float* bq = (const float*)d_in[4];
    const float* wk = (const float*)d_in[5];
    const float* bk = (const float*)d_in[6];
    const float* wv = (const float*)d_in[7];
    const float* bv = (const float*)d_in[8];
    const float* wo = (const float*)d_in[9];
    const float* bo = (const float*)d_in[10];
    float* out = (float*)d_out;

    ushort_t *xqh, *xql, *xkh, *xkl, *xvh, *xvl;
    ushort_t *wqh, *wql, *wkh, *wkl, *wvh, *wvl, *woh, *wol;
    ushort_t *Qh, *Ql, *Kh, *Kl, *Vh, *Vl, *Ch, *Cl;
    cudaGetSymbolAddress((void**)&xqh, g_xq_hi); cudaGetSymbolAddress((void**)&xql, g_xq_lo);
    cudaGetSymbolAddress((void**)&xkh, g_xk_hi); cudaGetSymbolAddress((void**)&xkl, g_xk_lo);
    cudaGetSymbolAddress((void**)&xvh, g_xv_hi); cudaGetSymbolAddress((void**)&xvl, g_xv_lo);
    cudaGetSymbolAddress((void**)&wqh, g_wq_hi); cudaGetSymbolAddress((void**)&wql, g_wq_lo);
    cudaGetSymbolAddress((void**)&wkh, g_wk_hi); cudaGetSymbolAddress((void**)&wkl, g_wk_lo);
    cudaGetSymbolAddress((void**)&wvh, g_wv_hi); cudaGetSymbolAddress((void**)&wvl, g_wv_lo);
    cudaGetSymbolAddress((void**)&woh, g_wo_hi); cudaGetSymbolAddress((void**)&wol, g_wo_lo);
    cudaGetSymbolAddress((void**)&Qh, g_Q_hi);   cudaGetSymbolAddress((void**)&Ql, g_Q_lo);
    cudaGetSymbolAddress((void**)&Kh, g_K_hi);   cudaGetSymbolAddress((void**)&Kl, g_K_lo);
    cudaGetSymbolAddress((void**)&Vh, g_V_hi);   cudaGetSymbolAddress((void**)&Vl, g_V_lo);
    cudaGetSymbolAddress((void**)&Ch, g_C_hi);   cudaGetSymbolAddress((void**)&Cl, g_C_lo);

    cudaFuncSetAttribute(gemm_bf16_kernel<0>,
                         cudaFuncAttributeMaxDynamicSharedMemorySize, GSM_TOTAL);
    cudaFuncSetAttribute(gemm_bf16_kernel<1>,
                         cudaFuncAttributeMaxDynamicSharedMemorySize, GSM_TOTAL);
    cudaFuncSetAttribute(attn_mma_kernel,
                         cudaFuncAttributeMaxDynamicSharedMemorySize, ASM_TOTAL);

    int dev = 0, nsm = 148;
    cudaGetDevice(&dev);
    cudaDeviceGetAttribute(&nsm, cudaDevAttrMultiProcessorCount, dev);
    const int pgrid = 2 * nsm;

    // 1. Convert inputs + weights to hi/lo bf16 (ONE launch) + reset tickets
    const int n4_in = NROWS * DMODEL / 4;      // 1,048,576
    const int n4_w  = DMODEL * DMODEL / 4;     // 262,144
    {
        CvtBatch cb = {};
        cb.x[0] = query; cb.hi[0] = xqh; cb.lo[0] = xql; cb.n4[0] = n4_in;
        cb.x[1] = key_;  cb.hi[1] = xkh; cb.lo[1] = xkl; cb.n4[1] = n4_in;
        cb.x[2] = value; cb.hi[2] = xvh; cb.lo[2] = xvl; cb.n4[2] = n4_in;
        cb.x[3] = wq;    cb.hi[3] = wqh; cb.lo[3] = wql; cb.n4[3] = n4_w;
        cb.x[4] = wk;    cb.hi[4] = wkh; cb.lo[4] = wkl; cb.n4[4] = n4_w;
        cb.x[5] = wv;    cb.hi[5] = wvh; cb.lo[5] = wvl; cb.n4[5] = n4_w;
        cb.x[6] = wo;    cb.hi[6] = woh; cb.lo[6] = wol; cb.n4[6] = n4_w;
        dim3 g(n4_in / 256, 7);
        cvt_multi_kernel<<<g, 256>>>(cb);
    }

    // 2. Fused QKV projections (persistent, 768 tiles, ticket 0).
    //    Q output pre-scaled by (1/8)*log2(e).
    {
        GemmBatch gb = {};
        gb.Ahi[0] = xqh; gb.Alo[0] = xql; gb.Bhi[0] = wqh; gb.Blo[0] = wql;
        gb.bias[0] = bq; gb.Chi[0] = Qh;  gb.Clo[0] = Ql;  gb.oscale[0] = SC_LOG2;
        gb.Ahi[1] = xkh; gb.Alo[1] = xkl; gb.Bhi[1] = wkh; gb.Blo[1] = wkl;
        gb.bias[1] = bk; gb.Chi[1] = Kh;  gb.Clo[1] = Kl;  gb.oscale[1] = 1.0f;
        gb.Ahi[2] = xvh; gb.Alo[2] = xvl; gb.Bhi[2] = wvh; gb.Blo[2] = wvl;
        gb.bias[2] = bv; gb.Chi[2] = Vh;  gb.Clo[2] = Vl;  gb.oscale[2] = 1.0f;
        gemm_bf16_kernel<1><<<pgrid, 256, GSM_TOTAL>>>(gb, nullptr, 768, 0);
    }

    // 3. Attention (persistent, 512 items, ticket 1)
    attn_mma_kernel<<<pgrid, 256, ASM_TOTAL>>>(Qh, Ql, Kh, Kl, Vh, Vl, Ch, Cl);

    // 4. Output projection (persistent, 256 tiles, ticket 2, fp32 out)
    {
        GemmBatch gb = {};
        gb.Ahi[0] = Ch; gb.Alo[0] = Cl; gb.Bhi[0] = woh; gb.Blo[0] = wol;
        gb.bias[0] = bo; gb.oscale[0] = 1.0f;
        gemm_bf16_kernel<0><<<pgrid, 256, GSM_TOTAL>>>(gb, out, 256, 2);
    }
}